// round 12
// baseline (speedup 1.0000x reference)
#include <cuda_runtime.h>

// GRUAdder: B=1048576, T=4, I=2, H=16
// out = concat(hidden_table[B,4,16], sum_logits[B,4], carry[B,1], output_logits[B,5]) fp32
// Split-j scheme: 2 threads per batch element (half 0: hidden units 0-7, half 1: 8-15),
// h exchanged through the smem staging that the coalesced store pass already requires.

static constexpr int BATCH   = 1048576;
static constexpr int TT      = 4;
static constexpr int HH      = 16;
static constexpr int KP      = 8;     // H/2 k-pairs
static constexpr int THREADS = 256;   // 128 columns x 2 halves
static constexpr int COLS    = 128;
static constexpr int ELEMS   = 2;     // batch elements per column
static constexpr int SPAN    = COLS * ELEMS;  // 256 elements per block (divides 2^20)
static constexpr int COLP    = COLS + 1;      // padded staging stride

typedef unsigned long long u64;

// ---- n-gate + head weights in constant memory (separate port from smem crossbar) ----
__constant__ __align__(16) float c_whhn[HH * HH]; // w_hh rows 32..47  [16][16]
__constant__ __align__(16) float c_wihn[HH * 2];  // w_ih rows 32..47  [16][2]
__constant__ __align__(16) float c_ws[HH];
__constant__ __align__(16) float c_wc[HH];
__constant__ float c_bs[1];
__constant__ float c_bc[1];

__device__ __forceinline__ u64 pack2(float lo, float hi) {
    u64 r; asm("mov.b64 %0, {%1, %2};" : "=l"(r) : "f"(lo), "f"(hi)); return r;
}
__device__ __forceinline__ float2 unpack2(u64 v) {
    float2 f; asm("mov.b64 {%0, %1}, %2;" : "=f"(f.x), "=f"(f.y) : "l"(v)); return f;
}
__device__ __forceinline__ void ffma2(u64 &d, u64 a, u64 b) {
    asm("fma.rn.f32x2 %0, %1, %2, %0;" : "+l"(d) : "l"(a), "l"(b));
}
__device__ __forceinline__ float hsum2(u64 v) { float2 f = unpack2(v); return f.x + f.y; }

__device__ __forceinline__ float tanh_fast(float x) {
    float y; asm("tanh.approx.f32 %0, %1;" : "=f"(y) : "f"(x)); return y;
}
__device__ __forceinline__ float sigmoid_fast(float x) {
    return fmaf(tanh_fast(0.5f * x), 0.5f, 0.5f);
}

__global__ void __launch_bounds__(THREADS, 3)
gru_adder_kernel(const float* __restrict__ x,       // [B,4,2]
                 const float* __restrict__ w_ih,    // [48,2]
                 const float* __restrict__ w_hh,    // [48,16]
                 const float* __restrict__ b_ih,    // [48]
                 const float* __restrict__ b_hh,    // [48]
                 float* __restrict__ out,
                 long long off_hid, long long off_sum,
                 long long off_car, long long off_log)
{
    // r,z hidden weights + biases + r,z input weights in SMEM (crossbar port)
    __shared__ __align__(16) u64 s_whh2[2 * HH][KP];   // rows 0..31 (r, z)
    __shared__ __align__(16) ulonglong2 s_wihrz[HH];   // { wih2[j], wih2[16+j] }
    __shared__ __align__(16) float4 s_bias4[HH];       // {b_r, b_z, b_ih_n, b_hh_n}
    __shared__ float s_hn[ELEMS][HH][COLP];            // new-h staging (padded)

    const int tid  = threadIdx.x;
    const int col  = tid & (COLS - 1);
    const int half = tid >> 7;            // 0 or 1
    const int jbase = half * 8;

    for (int i = tid; i < 2 * HH * KP; i += THREADS) {
        int g = i / KP, kk = i % KP;
        s_whh2[g][kk] = pack2(w_hh[g * HH + 2 * kk], w_hh[g * HH + 2 * kk + 1]);
    }
    if (tid < HH) {
        ulonglong2 wrz;
        wrz.x = pack2(w_ih[tid * 2],        w_ih[tid * 2 + 1]);
        wrz.y = pack2(w_ih[(16 + tid) * 2], w_ih[(16 + tid) * 2 + 1]);
        s_wihrz[tid] = wrz;
        s_bias4[tid] = make_float4(b_ih[tid] + b_hh[tid],
                                   b_ih[16 + tid] + b_hh[16 + tid],
                                   b_ih[32 + tid],
                                   b_hh[32 + tid]);
    }
    __syncthreads();

    const long long gbase = (long long)blockIdx.x * SPAN;   // SPAN divides BATCH: no guards
    long long idx[ELEMS];
#pragma unroll
    for (int e = 0; e < ELEMS; ++e) idx[e] = gbase + e * COLS + col;

    u64 h2[ELEMS][KP];
#pragma unroll
    for (int e = 0; e < ELEMS; ++e)
#pragma unroll
        for (int kk = 0; kk < KP; ++kk) h2[e][kk] = 0ull;

#pragma unroll
    for (int t = 0; t < TT; ++t) {
        u64 xt[ELEMS];
#pragma unroll
        for (int e = 0; e < ELEMS; ++e) {
            float2 xv = __ldg(reinterpret_cast<const float2*>(x + idx[e] * (TT * 2)) + t);
            xt[e] = pack2(xv.x, xv.y);
        }
        const bool hh_on = (t != 0);   // compile-time per unrolled copy

        // ----- rolled gate loop: this thread's 8 hidden units -----
#pragma unroll 1
        for (int jj = 0; jj < 8; ++jj) {
            const int j = jbase + jj;                 // warp-uniform
            const float4 bias = s_bias4[j];           // LDS.128 broadcast
            const ulonglong2 wrz = s_wihrz[j];        // LDS.128 broadcast
            const u64 wn0 = *reinterpret_cast<const u64*>(c_wihn + j * 2);  // const port

            u64 ar[ELEMS], az[ELEMS], an[ELEMS];
#pragma unroll
            for (int e = 0; e < ELEMS; ++e) {
                ar[e] = pack2(bias.x, 0.0f);
                az[e] = pack2(bias.y, 0.0f);
                an[e] = pack2(bias.w, 0.0f);
                ffma2(ar[e], wrz.x, xt[e]);
                ffma2(az[e], wrz.y, xt[e]);
            }

            if (hh_on) {
                const ulonglong2* wr  = reinterpret_cast<const ulonglong2*>(s_whh2[j]);       // smem
                const ulonglong2* wz  = reinterpret_cast<const ulonglong2*>(s_whh2[16 + j]);  // smem
                const ulonglong2* wnh = reinterpret_cast<const ulonglong2*>(c_whhn + j * HH); // const
#pragma unroll
                for (int q = 0; q < 4; ++q) {
                    ulonglong2 a = wr[q];
#pragma unroll
                    for (int e = 0; e < ELEMS; ++e) {
                        ffma2(ar[e], a.x, h2[e][2 * q]); ffma2(ar[e], a.y, h2[e][2 * q + 1]);
                    }
                    ulonglong2 b = wz[q];
#pragma unroll
                    for (int e = 0; e < ELEMS; ++e) {
                        ffma2(az[e], b.x, h2[e][2 * q]); ffma2(az[e], b.y, h2[e][2 * q + 1]);
                    }
                    ulonglong2 c = wnh[q];
#pragma unroll
                    for (int e = 0; e < ELEMS; ++e) {
                        ffma2(an[e], c.x, h2[e][2 * q]); ffma2(an[e], c.y, h2[e][2 * q + 1]);
                    }
                }
            }

#pragma unroll
            for (int e = 0; e < ELEMS; ++e) {
                float gr = hsum2(ar[e]);
                float gz = hsum2(az[e]);
                u64 ai = pack2(bias.z, 0.0f);
                ffma2(ai, wn0, xt[e]);
                float r = sigmoid_fast(gr);
                float np = hh_on ? (hsum2(ai) + r * hsum2(an[e]))
                                 : (hsum2(ai) + r * bias.w);
                float z = sigmoid_fast(gz);
                float n = tanh_fast(np);
                float2 hp = unpack2(h2[e][j >> 1]);
                float ho = (j & 1) ? hp.y : hp.x;
                s_hn[e][j][col] = n + z * (ho - n);
            }
        }

        __syncthreads();   // halves exchange h through staging

        // commit full new h (each thread needs all 16 units for its next-step matvec)
#pragma unroll
        for (int e = 0; e < ELEMS; ++e)
#pragma unroll
            for (int kk = 0; kk < KP; ++kk)
                h2[e][kk] = pack2(s_hn[e][2 * kk][col], s_hn[e][2 * kk + 1][col]);

        // ---- COALESCED hidden-table stores via staging smem ----
        if (off_hid >= 0) {
#pragma unroll
            for (int k = 0; k < 4; ++k) {
                int flat = k * THREADS + tid;       // 0..1023 = (elem_local, c4)
                int elem_local = flat >> 2;         // 0..255
                int c4 = (flat & 3) << 2;           // j0 in {0,4,8,12}
                int e = elem_local >> 7;
                int c = elem_local & (COLS - 1);
                long long g = gbase + elem_local;
                const float* sp = &s_hn[e][c4][c];
                float4 v = make_float4(sp[0], sp[COLP], sp[2 * COLP], sp[3 * COLP]);
                *reinterpret_cast<float4*>(out + off_hid + (g * TT + t) * HH + c4) = v;
            }
        }

        // sum logits: half 0 only (has full h2)
        if (half == 0) {
#pragma unroll
            for (int e = 0; e < ELEMS; ++e) {
                u64 sa = pack2(c_bs[0], 0.0f);
#pragma unroll
                for (int kk = 0; kk < KP; ++kk)
                    ffma2(sa, *reinterpret_cast<const u64*>(c_ws + 2 * kk), h2[e][kk]);
                float sO = hsum2(sa);
                if (off_sum >= 0) out[off_sum + idx[e] * TT + t] = sO;
                if (off_log >= 0) out[off_log + idx[e] * (TT + 1) + t] = sO;
            }
        }

        __syncthreads();   // protect staging before next t overwrites
    }

    // carry head: half 0 only
    if (half == 0) {
#pragma unroll
        for (int e = 0; e < ELEMS; ++e) {
            u64 ca = pack2(c_bc[0], 0.0f);
#pragma unroll
            for (int kk = 0; kk < KP; ++kk)
                ffma2(ca, *reinterpret_cast<const u64*>(c_wc + 2 * kk), h2[e][kk]);
            float cO = hsum2(ca);
            if (off_car >= 0) out[off_car + idx[e]] = cO;
            if (off_log >= 0) out[off_log + idx[e] * (TT + 1) + TT] = cO;
        }
    }
}

extern "C" void kernel_launch(void* const* d_in, const int* in_sizes, int n_in,
                              void* d_out, int out_size)
{
    const float* x    = (const float*)d_in[0];
    const float* w_ih = (const float*)d_in[1];
    const float* w_hh = (const float*)d_in[2];
    const float* b_ih = (const float*)d_in[3];
    const float* b_hh = (const float*)d_in[4];
    float* out = (float*)d_out;

    // n-gate rows (32..47) + heads into constant memory (graph-capturable D2D)
    cudaMemcpyToSymbolAsync(c_whhn, (const char*)d_in[2] + 32 * HH * sizeof(float),
                            HH * HH * sizeof(float), 0, cudaMemcpyDeviceToDevice, 0);
    cudaMemcpyToSymbolAsync(c_wihn, (const char*)d_in[1] + 32 * 2 * sizeof(float),
                            HH * 2 * sizeof(float), 0, cudaMemcpyDeviceToDevice, 0);
    cudaMemcpyToSymbolAsync(c_ws, d_in[5], HH * sizeof(float), 0, cudaMemcpyDeviceToDevice, 0);
    cudaMemcpyToSymbolAsync(c_bs, d_in[6], sizeof(float), 0, cudaMemcpyDeviceToDevice, 0);
    cudaMemcpyToSymbolAsync(c_wc, d_in[7], HH * sizeof(float), 0, cudaMemcpyDeviceToDevice, 0);
    cudaMemcpyToSymbolAsync(c_bc, d_in[8], sizeof(float), 0, cudaMemcpyDeviceToDevice, 0);

    const long long HID = 0;
    const long long SUM = (long long)BATCH * TT * HH;          // 67108864
    const long long CAR = SUM + (long long)BATCH * TT;         // 71303168
    const long long LOG = CAR + (long long)BATCH;              // 72351744
    const long long FULL = LOG + (long long)BATCH * (TT + 1);  // 77594624

    long long oh = -1, os = -1, oc = -1, ol = -1;
    long long sz = (long long)out_size;
    if (sz == FULL)                               { oh = HID; os = SUM; oc = CAR; ol = LOG; }
    else if (sz == (long long)BATCH * TT * HH)    { oh = 0; }
    else if (sz == (long long)BATCH * (TT + 1))   { ol = 0; }
    else if (sz == (long long)BATCH * TT)         { os = 0; }
    else if (sz == (long long)BATCH)              { oc = 0; }
    else                                          { oh = HID; os = SUM; oc = CAR; ol = LOG; }

    const int blocks = BATCH / SPAN;   // 4096, exact
    gru_adder_kernel<<<blocks, THREADS>>>(x, w_ih, w_hh, b_ih, b_hh,
                                          out, oh, os, oc, ol);
}

// round 14
// speedup vs baseline: 1.2187x; 1.2187x over previous
#include <cuda_runtime.h>

// GRUAdder: B=1048576, T=4, I=2, H=16
// out = concat(hidden_table[B,4,16], sum_logits[B,4], carry[B,1], output_logits[B,5]) fp32

static constexpr int BATCH   = 1048576;
static constexpr int TT      = 4;
static constexpr int HH      = 16;
static constexpr int KP      = 8;    // H/2 k-pairs
static constexpr int THREADS = 128;
static constexpr int ELEMS   = 3;
static constexpr int SPAN    = THREADS * ELEMS;   // 384
static constexpr int COLP    = THREADS + 1;       // padded staging stride

typedef unsigned long long u64;

// ---- n-gate + head weights in constant memory (separate port from smem crossbar) ----
__constant__ __align__(16) float c_whhn[HH * HH]; // w_hh rows 32..47  [16][16]
__constant__ __align__(16) float c_wihn[HH * 2];  // w_ih rows 32..47  [16][2]
__constant__ __align__(16) float c_ws[HH];
__constant__ __align__(16) float c_wc[HH];
__constant__ float c_bs[1];
__constant__ float c_bc[1];

__device__ __forceinline__ u64 pack2(float lo, float hi) {
    u64 r; asm("mov.b64 %0, {%1, %2};" : "=l"(r) : "f"(lo), "f"(hi)); return r;
}
__device__ __forceinline__ float2 unpack2(u64 v) {
    float2 f; asm("mov.b64 {%0, %1}, %2;" : "=f"(f.x), "=f"(f.y) : "l"(v)); return f;
}
__device__ __forceinline__ void ffma2(u64 &d, u64 a, u64 b) {
    asm("fma.rn.f32x2 %0, %1, %2, %0;" : "+l"(d) : "l"(a), "l"(b));
}
__device__ __forceinline__ float hsum2(u64 v) { float2 f = unpack2(v); return f.x + f.y; }

__device__ __forceinline__ float tanh_fast(float x) {
    float y; asm("tanh.approx.f32 %0, %1;" : "=f"(y) : "f"(x)); return y;
}
__device__ __forceinline__ float sigmoid_fast(float x) {
    return fmaf(tanh_fast(0.5f * x), 0.5f, 0.5f);
}

__global__ void __launch_bounds__(THREADS, 5)
gru_adder_kernel(const float* __restrict__ x,       // [B,4,2]
                 const float* __restrict__ w_ih,    // [48,2]
                 const float* __restrict__ w_hh,    // [48,16]
                 const float* __restrict__ b_ih,    // [48]
                 const float* __restrict__ b_hh,    // [48]
                 float* __restrict__ ohid,          // hidden_table base (or null)
                 float* __restrict__ osum,          // sum_logits base (or null)
                 float* __restrict__ ocar,          // carry base (or null)
                 float* __restrict__ olog)          // output_logits base (or null)
{
    // r,z hidden weights + biases + r,z input weights in SMEM (crossbar port)
    __shared__ __align__(16) u64 s_whh2[2 * HH][KP];   // rows 0..31 (r, z)
    __shared__ __align__(16) ulonglong2 s_wihrz[HH];   // { wih2[j], wih2[16+j] }
    __shared__ __align__(16) float4 s_bias4[HH];       // {b_r, b_z, b_ih_n, b_hh_n}
    __shared__ float s_hn[ELEMS][HH][COLP];            // new-h staging (padded)

    const int tid = threadIdx.x;
    for (int i = tid; i < 2 * HH * KP; i += THREADS) {
        int g = i / KP, kk = i % KP;
        s_whh2[g][kk] = pack2(w_hh[g * HH + 2 * kk], w_hh[g * HH + 2 * kk + 1]);
    }
    if (tid < HH) {
        ulonglong2 wrz;
        wrz.x = pack2(w_ih[tid * 2],        w_ih[tid * 2 + 1]);
        wrz.y = pack2(w_ih[(16 + tid) * 2], w_ih[(16 + tid) * 2 + 1]);
        s_wihrz[tid] = wrz;
        s_bias4[tid] = make_float4(b_ih[tid] + b_hh[tid],
                                   b_ih[16 + tid] + b_hh[16 + tid],
                                   b_ih[32 + tid],
                                   b_hh[32 + tid]);
    }
    __syncthreads();

    // SPAN=384: validity per (block, e) is warp-uniform — no per-thread clamps.
    const int gbase = blockIdx.x * SPAN;            // fits in int (< 2^20)
    bool v[ELEMS];
#pragma unroll
    for (int e = 0; e < ELEMS; ++e)
        v[e] = (gbase + (e + 1) * THREADS) <= BATCH;

    u64 h2[ELEMS][KP];
#pragma unroll
    for (int e = 0; e < ELEMS; ++e)
#pragma unroll
        for (int kk = 0; kk < KP; ++kk) h2[e][kk] = 0ull;

#pragma unroll
    for (int t = 0; t < TT; ++t) {
        u64 xt[ELEMS];
#pragma unroll
        for (int e = 0; e < ELEMS; ++e) {
            if (v[e]) {   // uniform branch
                int ei = gbase + e * THREADS + tid;
                float2 xv = __ldg(reinterpret_cast<const float2*>(x + (size_t)ei * (TT * 2)) + t);
                xt[e] = pack2(xv.x, xv.y);
            } else {
                xt[e] = 0ull;
            }
        }
        const bool hh_on = (t != 0);   // compile-time per unrolled copy

        // ----- rolled gate loop (keeps registers bounded) -----
#pragma unroll 1
        for (int j = 0; j < HH; ++j) {
            const float4 bias = s_bias4[j];        // LDS.128
            const ulonglong2 wrz = s_wihrz[j];     // LDS.128
            const u64 wn0 = *reinterpret_cast<const u64*>(c_wihn + j * 2);  // const port

            u64 ar[ELEMS], az[ELEMS], an[ELEMS];
#pragma unroll
            for (int e = 0; e < ELEMS; ++e) {
                ar[e] = pack2(bias.x, 0.0f);
                az[e] = pack2(bias.y, 0.0f);
                an[e] = pack2(bias.w, 0.0f);
                ffma2(ar[e], wrz.x, xt[e]);
                ffma2(az[e], wrz.y, xt[e]);
            }

            if (hh_on) {
                const ulonglong2* wr  = reinterpret_cast<const ulonglong2*>(s_whh2[j]);       // smem
                const ulonglong2* wz  = reinterpret_cast<const ulonglong2*>(s_whh2[16 + j]);  // smem
                const ulonglong2* wnh = reinterpret_cast<const ulonglong2*>(c_whhn + j * HH); // const
#pragma unroll
                for (int q = 0; q < 4; ++q) {
                    ulonglong2 a = wr[q];     // LDS.128 feeds 6 FFMA2 (3 elems)
#pragma unroll
                    for (int e = 0; e < ELEMS; ++e) {
                        ffma2(ar[e], a.x, h2[e][2 * q]); ffma2(ar[e], a.y, h2[e][2 * q + 1]);
                    }
                    ulonglong2 b = wz[q];
#pragma unroll
                    for (int e = 0; e < ELEMS; ++e) {
                        ffma2(az[e], b.x, h2[e][2 * q]); ffma2(az[e], b.y, h2[e][2 * q + 1]);
                    }
                    ulonglong2 c = wnh[q];    // const port
#pragma unroll
                    for (int e = 0; e < ELEMS; ++e) {
                        ffma2(an[e], c.x, h2[e][2 * q]); ffma2(an[e], c.y, h2[e][2 * q + 1]);
                    }
                }
            }

#pragma unroll
            for (int e = 0; e < ELEMS; ++e) {
                float gr = hsum2(ar[e]);
                float gz = hsum2(az[e]);
                u64 ai = pack2(bias.z, 0.0f);
                ffma2(ai, wn0, xt[e]);
                float r = sigmoid_fast(gr);
                float np = hh_on ? (hsum2(ai) + r * hsum2(an[e]))
                                 : (hsum2(ai) + r * bias.w);
                float z = sigmoid_fast(gz);
                float n = tanh_fast(np);
                float2 hp = unpack2(h2[e][j >> 1]);
                float ho = (j & 1) ? hp.y : hp.x;
                s_hn[e][j][tid] = n + z * (ho - n);
            }
        }

        // commit staged new h (own column only — no race before barrier)
#pragma unroll
        for (int e = 0; e < ELEMS; ++e)
#pragma unroll
            for (int kk = 0; kk < KP; ++kk)
                h2[e][kk] = pack2(s_hn[e][2 * kk][tid], s_hn[e][2 * kk + 1][tid]);

        // ---- COALESCED hidden-table stores via staging smem ----
        if (ohid != nullptr) {
            __syncthreads();   // staging visible to all threads (block-uniform branch)
#pragma unroll
            for (int k = 0; k < 12; ++k) {
                int flat = k * THREADS + tid;       // 0..1535 = (elem_local, c4)
                int elem_local = flat >> 2;         // 0..383
                int c4 = (flat & 3) << 2;           // j0 in {0,4,8,12}
                int e = elem_local >> 7;
                int col = elem_local & 127;
                int g = gbase + elem_local;
                if (g < BATCH) {
                    const float* sp = &s_hn[e][c4][col];
                    float4 val = make_float4(sp[0], sp[COLP], sp[2 * COLP], sp[3 * COLP]);
                    *reinterpret_cast<float4*>(ohid + ((size_t)g * TT + t) * HH + c4) = val;
                }
            }
            __syncthreads();   // protect staging before next t overwrites
        }

        // sum logits + small scattered stores (head weights from const)
#pragma unroll
        for (int e = 0; e < ELEMS; ++e) {
            if (v[e]) {   // uniform branch
                u64 sa = pack2(c_bs[0], 0.0f);
#pragma unroll
                for (int kk = 0; kk < KP; ++kk)
                    ffma2(sa, *reinterpret_cast<const u64*>(c_ws + 2 * kk), h2[e][kk]);
                float sO = hsum2(sa);
                int ei = gbase + e * THREADS + tid;
                if (osum != nullptr) osum[(size_t)ei * TT + t] = sO;
                if (olog != nullptr) olog[(size_t)ei * (TT + 1) + t] = sO;
            }
        }
    }

    // carry head
#pragma unroll
    for (int e = 0; e < ELEMS; ++e) {
        if (v[e]) {   // uniform branch
            u64 ca = pack2(c_bc[0], 0.0f);
#pragma unroll
            for (int kk = 0; kk < KP; ++kk)
                ffma2(ca, *reinterpret_cast<const u64*>(c_wc + 2 * kk), h2[e][kk]);
            float cO = hsum2(ca);
            int ei = gbase + e * THREADS + tid;
            if (ocar != nullptr) ocar[ei] = cO;
            if (olog != nullptr) olog[(size_t)ei * (TT + 1) + TT] = cO;
        }
    }
}

extern "C" void kernel_launch(void* const* d_in, const int* in_sizes, int n_in,
                              void* d_out, int out_size)
{
    const float* x    = (const float*)d_in[0];
    const float* w_ih = (const float*)d_in[1];
    const float* w_hh = (const float*)d_in[2];
    const float* b_ih = (const float*)d_in[3];
    const float* b_hh = (const float*)d_in[4];
    float* out = (float*)d_out;

    // n-gate rows (32..47) + heads into constant memory (graph-capturable D2D)
    cudaMemcpyToSymbolAsync(c_whhn, (const char*)d_in[2] + 32 * HH * sizeof(float),
                            HH * HH * sizeof(float), 0, cudaMemcpyDeviceToDevice, 0);
    cudaMemcpyToSymbolAsync(c_wihn, (const char*)d_in[1] + 32 * 2 * sizeof(float),
                            HH * 2 * sizeof(float), 0, cudaMemcpyDeviceToDevice, 0);
    cudaMemcpyToSymbolAsync(c_ws, d_in[5], HH * sizeof(float), 0, cudaMemcpyDeviceToDevice, 0);
    cudaMemcpyToSymbolAsync(c_bs, d_in[6], sizeof(float), 0, cudaMemcpyDeviceToDevice, 0);
    cudaMemcpyToSymbolAsync(c_wc, d_in[7], HH * sizeof(float), 0, cudaMemcpyDeviceToDevice, 0);
    cudaMemcpyToSymbolAsync(c_bc, d_in[8], sizeof(float), 0, cudaMemcpyDeviceToDevice, 0);

    const long long SUM = (long long)BATCH * TT * HH;          // 67108864
    const long long CAR = SUM + (long long)BATCH * TT;         // 71303168
    const long long LOG = CAR + (long long)BATCH;              // 72351744
    const long long FULL = LOG + (long long)BATCH * (TT + 1);  // 77594624

    float *ohid = nullptr, *osum = nullptr, *ocar = nullptr, *olog = nullptr;
    long long sz = (long long)out_size;
    if (sz == FULL) { ohid = out; osum = out + SUM; ocar = out + CAR; olog = out + LOG; }
    else if (sz == (long long)BATCH * TT * HH)  { ohid = out; }
    else if (sz == (long long)BATCH * (TT + 1)) { olog = out; }
    else if (sz == (long long)BATCH * TT)       { osum = out; }
    else if (sz == (long long)BATCH)            { ocar = out; }
    else            { ohid = out; osum = out + SUM; ocar = out + CAR; olog = out + LOG; }

    const int blocks = (BATCH + SPAN - 1) / SPAN;   // 2731
    gru_adder_kernel<<<blocks, THREADS>>>(x, w_ih, w_hh, b_ih, b_hh,
                                          ohid, osum, ocar, olog);
}